// round 5
// baseline (speedup 1.0000x reference)
#include <cuda_runtime.h>

// Problem constants (fixed by setup_inputs)
#define T_LEN 8192
#define H_HEADS 16
#define B_BATCH 2
#define P_DIM 64
#define N_DIM 64
#define BH (B_BATCH * H_HEADS)   // 32

#define KS 32                    // timesteps per state slice
#define NSLICE (T_LEN / KS)      // 256
#define THRESH 45.0f             // exp(-45) ~ 3e-20: utterly negligible
#define TSTEP 128                // t-rows per prep-A block

// Scratch (allocation-free rule: device globals)
__device__ float g_chunk[BH * NSLICE];  // per-slice sums of A
__device__ float g_tail[BH * NSLICE];   // suffix sum of A beyond each slice

// ---- packed fp32x2 helpers (sm_100+; PTX-only, ptxas won't auto-fuse) ----
__device__ __forceinline__ unsigned long long fma2(unsigned long long a,
                                                   unsigned long long b,
                                                   unsigned long long c) {
    unsigned long long d;
    asm("fma.rn.f32x2 %0, %1, %2, %3;" : "=l"(d) : "l"(a), "l"(b), "l"(c));
    return d;
}
__device__ __forceinline__ unsigned long long pack2(float x) {
    unsigned long long d;
    asm("mov.b64 %0, {%1, %1};" : "=l"(d) : "f"(x));
    return d;
}

// ---------------------------------------------------------------------------
// Prep A: coalesced chunk sums via float4. A is [b, T, h]; (t,h) contiguous.
// grid = (T/128, B), 256 threads; block covers 128 t x 16 h -> 4 chunk sums/h.
// ---------------------------------------------------------------------------
__global__ void __launch_bounds__(256)
prepA_kernel(const float* __restrict__ A) {
    int b = blockIdx.y;
    int t0 = blockIdx.x * TSTEP;
    int tid = threadIdx.x;

    __shared__ float s_tile[TSTEP * 16];   // [t][h], 16-wide rows (float4 ops)
    __shared__ float s_part[256];

    const float4* Ab4 = (const float4*)(A + ((size_t)b * T_LEN + t0) * H_HEADS);
    ((float4*)s_tile)[tid]       = Ab4[tid];
    ((float4*)s_tile)[tid + 256] = Ab4[tid + 256];
    __syncthreads();

    // thread = (chunk c: 2b, sub: 2b, h: 4b); each sums 8 t-values
    int c   = tid >> 6;
    int sub = (tid >> 4) & 3;
    int h   = tid & 15;
    float s = 0.f;
#pragma unroll
    for (int r = 0; r < 8; r++)
        s += s_tile[(c * 32 + sub * 8 + r) * 16 + h];
    s_part[tid] = s;
    __syncthreads();

    if (sub == 0) {
        float tot = s_part[tid] + s_part[tid + 16] + s_part[tid + 32] + s_part[tid + 48];
        int slice = blockIdx.x * 4 + c;
        int bh = b * H_HEADS + h;
        g_chunk[bh * NSLICE + slice] = tot;
    }
}

// ---------------------------------------------------------------------------
// Prep B: per bh, suffix-scan 256 chunk sums -> tails. Also zero output.
// ---------------------------------------------------------------------------
__global__ void __launch_bounds__(NSLICE)
prepB_kernel(float* __restrict__ out) {
    int bh = blockIdx.x;
    int tid = threadIdx.x;

    __shared__ float s[NSLICE];
    s[tid] = g_chunk[bh * NSLICE + tid];

    float* ob = out + (size_t)bh * (P_DIM * N_DIM);
#pragma unroll
    for (int i = 0; i < (P_DIM * N_DIM) / NSLICE; i++)
        ob[tid + i * NSLICE] = 0.f;

    __syncthreads();
#pragma unroll
    for (int off = 1; off < NSLICE; off <<= 1) {
        float add = (tid + off < NSLICE) ? s[tid + off] : 0.f;
        __syncthreads();
        s[tid] += add;
        __syncthreads();
    }
    g_tail[bh * NSLICE + tid] = (tid + 1 < NSLICE) ? s[tid + 1] : 0.f;
}

// ---------------------------------------------------------------------------
// State: per (slice, bh): S[64p,64n] += sum_t w_t X[t,p] B[t,n]
// 64 threads, 8x8 register tile, packed f32x2 FMA, red.v4 epilogue.
// ---------------------------------------------------------------------------
__global__ void __launch_bounds__(64)
state_kernel(const float* __restrict__ X, const float* __restrict__ Bm,
             const float* __restrict__ A, float* __restrict__ out) {
    int bh = blockIdx.y;
    int slice = blockIdx.x;
    float tail = g_tail[bh * NSLICE + slice];
    if (tail < -THRESH) return;

    int b = bh / H_HEADS, hh = bh % H_HEADS;
    int tid = threadIdx.x;
    int t0 = slice * KS;

    __shared__ float s_a[KS];
    __shared__ float s_wt[KS];
    __shared__ float sX[KS][P_DIM];
    __shared__ float sB[KS][N_DIM];

    if (tid < KS)
        s_a[tid] = A[((size_t)b * T_LEN + t0 + tid) * H_HEADS + hh];

    // gmem tile loads (64 thr -> 4 rows x 16 float4 per pass, 8 passes)
    int lrow = tid >> 4, lcol = (tid & 15) << 2;
    float4 xr[8], br[8];
#pragma unroll
    for (int k = 0; k < 8; k++) {
        int r = k * 4 + lrow;
        size_t goff = (((size_t)b * T_LEN + t0 + r) * H_HEADS + hh) * P_DIM + lcol;
        xr[k] = *(const float4*)(X + goff);
        br[k] = *(const float4*)(Bm + goff);
    }
    __syncthreads();   // s_a visible

    if (tid < KS) {
        float s = tail;
        for (int j = tid + 1; j < KS; j++) s += s_a[j];
        s_wt[tid] = expf(s);
    }
    __syncthreads();   // s_wt visible

#pragma unroll
    for (int k = 0; k < 8; k++) {
        int r = k * 4 + lrow;
        float w = s_wt[r];
        float4 xv = xr[k];
        xv.x *= w; xv.y *= w; xv.z *= w; xv.w *= w;
        *(float4*)&sX[r][lcol] = xv;
        *(float4*)&sB[r][lcol] = br[k];
    }
    __syncthreads();

    // 8x8 register tile: p0,n0 in {0,8,...,56}
    int p0 = (tid >> 3) << 3;
    int n0 = (tid & 7) << 3;
    unsigned long long acc[8][4] = {};   // [p-row][n-pair], f32x2

#pragma unroll
    for (int tt = 0; tt < KS; tt++) {
        float4 x0 = *(const float4*)&sX[tt][p0];
        float4 x1 = *(const float4*)&sX[tt][p0 + 4];
        ulonglong2 b0 = *(const ulonglong2*)&sB[tt][n0];      // packed n-pairs
        ulonglong2 b1 = *(const ulonglong2*)&sB[tt][n0 + 4];
        unsigned long long bv[4] = {b0.x, b0.y, b1.x, b1.y};
        float xs[8] = {x0.x, x0.y, x0.z, x0.w, x1.x, x1.y, x1.z, x1.w};
#pragma unroll
        for (int i = 0; i < 8; i++) {
            unsigned long long x2 = pack2(xs[i]);
#pragma unroll
            for (int j = 0; j < 4; j++)
                acc[i][j] = fma2(x2, bv[j], acc[i][j]);
        }
    }

    // epilogue: unpack pairs, 2 x red.v4 per output row
    float* ob = out + (size_t)bh * (P_DIM * N_DIM);
#pragma unroll
    for (int i = 0; i < 8; i++) {
        float v[8];
#pragma unroll
        for (int j = 0; j < 4; j++)
            asm("mov.b64 {%0, %1}, %2;" : "=f"(v[2 * j]), "=f"(v[2 * j + 1])
                                        : "l"(acc[i][j]));
        float* p = &ob[(p0 + i) * N_DIM + n0];
        asm volatile("red.global.add.v4.f32 [%0], {%1, %2, %3, %4};"
                     :: "l"(p), "f"(v[0]), "f"(v[1]), "f"(v[2]), "f"(v[3]) : "memory");
        asm volatile("red.global.add.v4.f32 [%0], {%1, %2, %3, %4};"
                     :: "l"(p + 4), "f"(v[4]), "f"(v[5]), "f"(v[6]), "f"(v[7]) : "memory");
    }
}

// ---------------------------------------------------------------------------
extern "C" void kernel_launch(void* const* d_in, const int* in_sizes, int n_in,
                              void* d_out, int out_size) {
    const float* X = (const float*)d_in[0];
    const float* A = (const float*)d_in[1];
    const float* B = (const float*)d_in[2];
    float* out = (float*)d_out;

    dim3 gA(T_LEN / TSTEP, B_BATCH);
    prepA_kernel<<<gA, 256>>>(A);
    prepB_kernel<<<BH, NSLICE>>>(out);
    dim3 gS(NSLICE, BH);
    state_kernel<<<gS, 64>>>(X, B, A, out);
}